// round 6
// baseline (speedup 1.0000x reference)
#include <cuda_runtime.h>
#include <math.h>

#define Bn 2
#define Cn 64
#define Hn 192
#define Wn 192
#define HWn (Hn*Wn)
#define Gn 4
#define CGn 16
#define Kn 9
#define WP 72   // padded weight row (64 + 8) -> conflict-free across q

typedef unsigned long long ull;

// Scratch
__device__ float g_xnhwc[Bn*HWn*Cn];          // NHWC warp_ref
__device__ float g_mod[Bn*Gn*Kn*HWn];         // modulator
__device__ float g_wT[Gn*Kn*CGn*Cn];          // reg_w as [g][k][c][co]

// ---------- packed fp32x2 helpers ----------
__device__ __forceinline__ ull pk2(float x) {
    ull r; unsigned u = __float_as_uint(x);
    asm("mov.b64 %0, {%1, %1};" : "=l"(r) : "r"(u));
    return r;
}
__device__ __forceinline__ void fma2(ull& d, ull a, ull b) {
    asm("fma.rn.f32x2 %0, %1, %2, %0;" : "+l"(d) : "l"(a), "l"(b));
}
__device__ __forceinline__ float2 upk(ull p) {
    unsigned lo, hi;
    asm("mov.b64 {%0, %1}, %2;" : "=r"(lo), "=r"(hi) : "l"(p));
    return make_float2(__uint_as_float(lo), __uint_as_float(hi));
}

// ---------------------------------------------------------------------------
// NCHW -> NHWC transpose of warp_ref
// ---------------------------------------------------------------------------
__global__ void k_transpose(const float* __restrict__ x) {
    __shared__ float t[32][33];
    int b   = blockIdx.z;
    int hw0 = blockIdx.x * 32;
    int c0  = blockIdx.y * 32;
    #pragma unroll
    for (int i = 0; i < 4; i++) {
        int c = c0 + threadIdx.y + i*8;
        t[threadIdx.y + i*8][threadIdx.x] = x[(b*Cn + c)*HWn + hw0 + threadIdx.x];
    }
    __syncthreads();
    #pragma unroll
    for (int i = 0; i < 4; i++) {
        int hw = hw0 + threadIdx.y + i*8;
        g_xnhwc[(size_t)(b*HWn + hw)*Cn + c0 + threadIdx.x] = t[threadIdx.x][threadIdx.y + i*8];
    }
}

// reg_w [co][cin][k] -> g_wT [g][k][c][co]
__global__ void k_wprep(const float* __restrict__ rw) {
    int i = blockIdx.x*256 + threadIdx.x;
    if (i >= Gn*Kn*CGn*Cn) return;
    int g = i / (Kn*CGn*Cn);
    int r = i % (Kn*CGn*Cn);
    int k = r / (CGn*Cn);
    int c = (r / Cn) % CGn;
    int co = r % Cn;
    g_wT[i] = rw[(size_t)(co*Cn + g*CGn + c)*Kn + k];
}

// ---------------------------------------------------------------------------
// Offset conv (known good).
// ---------------------------------------------------------------------------
__global__ void k_offset(const float* __restrict__ wr, const float* __restrict__ src,
                         const float* __restrict__ ow, const float* __restrict__ ob,
                         float* __restrict__ offout) {
    __shared__ float sT[8*18*35];
    __shared__ float sWp[8*9*20];
    int tid = threadIdx.x;
    int g = blockIdx.y, b = blockIdx.z;
    int th = (blockIdx.x / 6) * 16, tw = (blockIdx.x % 6) * 32;
    int lyy = tid >> 4, lxx = tid & 15;

    float4 acc0[5], acc1[5];
    #pragma unroll
    for (int j = 0; j < 5; j++) { acc0[j] = make_float4(0,0,0,0); acc1[j] = make_float4(0,0,0,0); }

    for (int chunk = 0; chunk < 4; chunk++) {
        const float* base = (chunk < 2 ? wr : src) + (size_t)(b*Cn + g*CGn + (chunk&1)*8)*HWn;
        __syncthreads();
        for (int i = tid; i < 1440; i += 256) {
            int c = i / 180; int r = i % 180; int widx = r / 20; int o = r % 20;
            float v = 0.f;
            if (o < 18) v = ow[(size_t)(o*32 + chunk*8 + c)*9 + widx];
            sWp[i] = v;
        }
        for (int i = tid; i < 8*18*35; i += 256) {
            int c = i / 630; int r2 = i % 630; int rr = r2 / 35; int cc = r2 % 35;
            int y = th + rr - 1, x = tw + cc - 1;
            float v = 0.f;
            if (cc < 34 && (unsigned)y < (unsigned)Hn && (unsigned)x < (unsigned)Wn)
                v = base[c*HWn + y*Wn + x];
            sT[i] = v;
        }
        __syncthreads();
        for (int c = 0; c < 8; c++) {
            #pragma unroll
            for (int kh = 0; kh < 3; kh++) {
                const float* rowp = sT + c*630 + (lyy+kh)*35 + 2*lxx;
                float xv[4];
                xv[0] = rowp[0]; xv[1] = rowp[1]; xv[2] = rowp[2]; xv[3] = rowp[3];
                #pragma unroll
                for (int kw = 0; kw < 3; kw++) {
                    const float4* wp = (const float4*)(sWp + (c*9 + kh*3 + kw)*20);
                    float a0 = xv[kw], a1 = xv[kw+1];
                    #pragma unroll
                    for (int j = 0; j < 5; j++) {
                        float4 wv = wp[j];
                        acc0[j].x = fmaf(a0, wv.x, acc0[j].x); acc1[j].x = fmaf(a1, wv.x, acc1[j].x);
                        acc0[j].y = fmaf(a0, wv.y, acc0[j].y); acc1[j].y = fmaf(a1, wv.y, acc1[j].y);
                        acc0[j].z = fmaf(a0, wv.z, acc0[j].z); acc1[j].z = fmaf(a1, wv.z, acc1[j].z);
                        acc0[j].w = fmaf(a0, wv.w, acc0[j].w); acc1[j].w = fmaf(a1, wv.w, acc1[j].w);
                    }
                }
            }
        }
    }
    int h = th + lyy, w = tw + 2*lxx;
    const float* a0 = (const float*)acc0;
    const float* a1 = (const float*)acc1;
    #pragma unroll
    for (int o = 0; o < 18; o++) {
        float bo = ob[o];
        float2 r;
        r.x = 50.f * tanhf(0.5f * (a0[o] + bo));
        r.y = 50.f * tanhf(0.5f * (a1[o] + bo));
        *(float2*)(offout + (size_t)(b*72 + g*18 + o)*HWn + h*Wn + w) = r;
    }
}

// ---------------------------------------------------------------------------
// Modulator conv (known good).
// ---------------------------------------------------------------------------
__global__ void k_mod(const float* __restrict__ wr, const float* __restrict__ mw,
                      const float* __restrict__ mb) {
    __shared__ float sT[8*18*35];
    __shared__ float sWp[8*9*20];
    int tid = threadIdx.x;
    int obase = blockIdx.y * 18;
    int b = blockIdx.z;
    int th = (blockIdx.x / 6) * 16, tw = (blockIdx.x % 6) * 32;
    int lyy = tid >> 4, lxx = tid & 15;

    float4 acc0[5], acc1[5];
    #pragma unroll
    for (int j = 0; j < 5; j++) { acc0[j] = make_float4(0,0,0,0); acc1[j] = make_float4(0,0,0,0); }

    for (int chunk = 0; chunk < 8; chunk++) {
        const float* base = wr + (size_t)(b*Cn + chunk*8)*HWn;
        __syncthreads();
        for (int i = tid; i < 1440; i += 256) {
            int c = i / 180; int r = i % 180; int widx = r / 20; int o = r % 20;
            float v = 0.f;
            if (o < 18) v = mw[(size_t)((obase + o)*Cn + chunk*8 + c)*9 + widx];
            sWp[i] = v;
        }
        for (int i = tid; i < 8*18*35; i += 256) {
            int c = i / 630; int r2 = i % 630; int rr = r2 / 35; int cc = r2 % 35;
            int y = th + rr - 1, x = tw + cc - 1;
            float v = 0.f;
            if (cc < 34 && (unsigned)y < (unsigned)Hn && (unsigned)x < (unsigned)Wn)
                v = base[c*HWn + y*Wn + x];
            sT[i] = v;
        }
        __syncthreads();
        for (int c = 0; c < 8; c++) {
            #pragma unroll
            for (int kh = 0; kh < 3; kh++) {
                const float* rowp = sT + c*630 + (lyy+kh)*35 + 2*lxx;
                float xv[4];
                xv[0] = rowp[0]; xv[1] = rowp[1]; xv[2] = rowp[2]; xv[3] = rowp[3];
                #pragma unroll
                for (int kw = 0; kw < 3; kw++) {
                    const float4* wp = (const float4*)(sWp + (c*9 + kh*3 + kw)*20);
                    float a0 = xv[kw], a1 = xv[kw+1];
                    #pragma unroll
                    for (int j = 0; j < 5; j++) {
                        float4 wv = wp[j];
                        acc0[j].x = fmaf(a0, wv.x, acc0[j].x); acc1[j].x = fmaf(a1, wv.x, acc1[j].x);
                        acc0[j].y = fmaf(a0, wv.y, acc0[j].y); acc1[j].y = fmaf(a1, wv.y, acc1[j].y);
                        acc0[j].z = fmaf(a0, wv.z, acc0[j].z); acc1[j].z = fmaf(a1, wv.z, acc1[j].z);
                        acc0[j].w = fmaf(a0, wv.w, acc0[j].w); acc1[j].w = fmaf(a1, wv.w, acc1[j].w);
                    }
                }
            }
        }
    }
    int h = th + lyy, w = tw + 2*lxx;
    const float* a0 = (const float*)acc0;
    const float* a1 = (const float*)acc1;
    #pragma unroll
    for (int o = 0; o < 18; o++) {
        float bo = mb[obase + o];
        float2 r;
        r.x = 1.f + tanhf(0.5f * (a0[o] + bo));
        r.y = 1.f + tanhf(0.5f * (a1[o] + bo));
        *(float2*)(g_mod + (size_t)(b*36 + obase + o)*HWn + h*Wn + w) = r;
    }
}

// ---------------------------------------------------------------------------
// Deformable conv, exchange-free. Thread = (pixel, channel-quad q).
// Lane q gathers channels q*4..q*4+3 of its pixel (4 lanes/pixel -> 64B
// contiguous per bilinear corner) and contracts them into ALL 64 output
// channels (32 f32x2 partial accumulators). No shfl/barrier in the k loop;
// one butterfly reduction over the 4 q-lanes at the end.
// Weight rows padded to WP=72 floats -> q-rows hit banks {0,8,16,24}.
// ---------------------------------------------------------------------------
__global__ void __launch_bounds__(256) k_deform(
        const float* __restrict__ offmap, float* __restrict__ out) {
    __shared__ float sW[Kn*CGn*WP];  // [k][c][co pad 72] = 10368 floats (40.5 KB)
    int tid  = threadIdx.x;
    int lane = tid & 31;
    int pxw  = lane >> 2;            // pixel within warp (0..7)
    int q    = lane & 3;             // channel-quad (0..3)
    int px   = (tid >> 5)*8 + pxw;   // pixel within block (0..63)
    int p0   = blockIdx.x * 64;
    int b    = p0 / HWn;
    int hw   = p0 - b*HWn + px;
    int h    = hw / Wn, w = hw - h*Wn;

    ull acc[32];
    #pragma unroll
    for (int j = 0; j < 32; j++) acc[j] = 0ull;

    const float* xb = g_xnhwc + (size_t)b*HWn*Cn;

    for (int g = 0; g < Gn; g++) {
        __syncthreads();
        for (int i = tid; i < Kn*CGn*WP; i += 256) {
            int co = i % WP;
            int kc = i / WP;                 // k*16 + c
            sW[i] = (co < Cn) ? g_wT[g*(Kn*CGn*Cn) + kc*Cn + co] : 0.f;
        }
        __syncthreads();

        const float* offb = offmap + (size_t)(b*72 + g*18)*HWn + hw;
        const float* modb = g_mod  + (size_t)(b*36 + g*9 )*HWn + hw;
        const float* xg   = xb + g*CGn + q*4;

        #pragma unroll 1
        for (int k = 0; k < 9; k++) {
            // ---- gather: this lane's 4 channels of its pixel ----
            float oy = offb[(2*k  )*HWn];
            float ox = offb[(2*k+1)*HWn];
            float m  = modb[k*HWn];
            float yf = oy + (float)(k/3 + h - 1);
            float xf = ox + (float)(k%3 + w - 1);
            float y0f = floorf(yf), x0f = floorf(xf);
            int   y0  = (int)y0f,   x0  = (int)x0f;
            float ly = yf - y0f, lx = xf - x0f;
            float cw0 = (1.f-ly)*(1.f-lx)*m;
            float cw1 = (1.f-ly)*lx*m;
            float cw2 = ly*(1.f-lx)*m;
            float cw3 = ly*lx*m;
            float4 v = make_float4(0.f,0.f,0.f,0.f);
            #pragma unroll
            for (int corner = 0; corner < 4; corner++) {
                int yi = y0 + (corner >> 1);
                int xi = x0 + (corner & 1);
                float wc = (corner==0)?cw0:(corner==1)?cw1:(corner==2)?cw2:cw3;
                if ((unsigned)yi < (unsigned)Hn && (unsigned)xi < (unsigned)Wn) {
                    float4 xv = *(const float4*)(xg + (size_t)(yi*Wn + xi)*Cn);
                    v.x = fmaf(wc, xv.x, v.x);
                    v.y = fmaf(wc, xv.y, v.y);
                    v.z = fmaf(wc, xv.z, v.z);
                    v.w = fmaf(wc, xv.w, v.w);
                }
            }
            // ---- contract my 4 channels into all 64 co ----
            const float* wk = sW + (k*CGn + q*4)*WP;
            float cv[4] = {v.x, v.y, v.z, v.w};
            #pragma unroll
            for (int cc = 0; cc < 4; cc++) {
                ull vp = pk2(cv[cc]);
                const ulonglong2* wp = (const ulonglong2*)(wk + cc*WP);
                #pragma unroll
                for (int jj = 0; jj < 16; jj++) {
                    ulonglong2 wv = wp[jj];
                    fma2(acc[2*jj],   vp, wv.x);
                    fma2(acc[2*jj+1], vp, wv.y);
                }
            }
        }
    }

    // ---- one-time butterfly reduction over the 4 q-lanes of each pixel ----
    float2 af[32];
    #pragma unroll
    for (int t = 0; t < 32; t++) af[t] = upk(acc[t]);
    #pragma unroll
    for (int t = 0; t < 32; t++) {
        af[t].x += __shfl_xor_sync(0xffffffffu, af[t].x, 1);
        af[t].y += __shfl_xor_sync(0xffffffffu, af[t].y, 1);
        af[t].x += __shfl_xor_sync(0xffffffffu, af[t].x, 2);
        af[t].y += __shfl_xor_sync(0xffffffffu, af[t].y, 2);
    }

    // lane q writes co pairs t = q*8 .. q*8+7
    float* ob = out + (size_t)b*Cn*HWn + hw;
    #pragma unroll
    for (int r = 0; r < 8; r++) {
        int t = q*8 + r;
        ob[(size_t)(2*t  )*HWn] = af[t].x;
        ob[(size_t)(2*t+1)*HWn] = af[t].y;
    }
}

// ---------------------------------------------------------------------------
extern "C" void kernel_launch(void* const* d_in, const int* in_sizes, int n_in,
                              void* d_out, int out_size) {
    const float* wr  = (const float*)d_in[0];
    const float* src = (const float*)d_in[1];
    const float* ow  = (const float*)d_in[2];
    const float* obv = (const float*)d_in[3];
    const float* mw  = (const float*)d_in[4];
    const float* mbv = (const float*)d_in[5];
    const float* rw  = (const float*)d_in[6];

    float* out    = (float*)d_out;
    float* offout = out + (size_t)Bn*Cn*HWn;

    k_transpose<<<dim3(HWn/32, 2, Bn), dim3(32, 8)>>>(wr);
    k_wprep   <<<(Gn*Kn*CGn*Cn + 255)/256, 256>>>(rw);
    k_offset  <<<dim3(72, Gn, Bn), 256>>>(wr, src, ow, obv, offout);
    k_mod     <<<dim3(72, 2, Bn), 256>>>(wr, mw, mbv);
    k_deform  <<<Bn*HWn/64, 256>>>(offout, out);
}

// round 7
// speedup vs baseline: 2.4958x; 2.4958x over previous
#include <cuda_runtime.h>
#include <math.h>

#define Bn 2
#define Cn 64
#define Hn 192
#define Wn 192
#define HWn (Hn*Wn)
#define Gn 4
#define CGn 16
#define Kn 9

typedef unsigned long long ull;

// Scratch
__device__ float g_xnhwc[Bn*HWn*Cn];           // NHWC warp_ref
__device__ float g_mod[Bn*Gn*Kn*HWn];          // modulator
__device__ float g_wTu[Gn*Kn*4*16*4*4];        // reg_w as [g][k][cc][j2][q][co4]

// ---------- packed fp32x2 helpers ----------
__device__ __forceinline__ ull pk2(float x) {
    ull r; unsigned u = __float_as_uint(x);
    asm("mov.b64 %0, {%1, %1};" : "=l"(r) : "r"(u));
    return r;
}
__device__ __forceinline__ void fma2(ull& d, ull a, ull b) {
    asm("fma.rn.f32x2 %0, %1, %2, %0;" : "+l"(d) : "l"(a), "l"(b));
}
__device__ __forceinline__ float2 upk(ull p) {
    unsigned lo, hi;
    asm("mov.b64 {%0, %1}, %2;" : "=r"(lo), "=r"(hi) : "l"(p));
    return make_float2(__uint_as_float(lo), __uint_as_float(hi));
}

// ---------------------------------------------------------------------------
// NCHW -> NHWC transpose of warp_ref
// ---------------------------------------------------------------------------
__global__ void k_transpose(const float* __restrict__ x) {
    __shared__ float t[32][33];
    int b   = blockIdx.z;
    int hw0 = blockIdx.x * 32;
    int c0  = blockIdx.y * 32;
    #pragma unroll
    for (int i = 0; i < 4; i++) {
        int c = c0 + threadIdx.y + i*8;
        t[threadIdx.y + i*8][threadIdx.x] = x[(b*Cn + c)*HWn + hw0 + threadIdx.x];
    }
    __syncthreads();
    #pragma unroll
    for (int i = 0; i < 4; i++) {
        int hw = hw0 + threadIdx.y + i*8;
        g_xnhwc[(size_t)(b*HWn + hw)*Cn + c0 + threadIdx.x] = t[threadIdx.x][threadIdx.y + i*8];
    }
}

// reg_w [co][cin][k] -> g_wTu [g][k][cc][j2][q][co4]
//   c (input ch within group) = q*4 + cc,  co (output ch) = j2*4 + co4
__global__ void k_wprep(const float* __restrict__ rw) {
    int i = blockIdx.x*256 + threadIdx.x;
    if (i >= Gn*Kn*4*16*4*4) return;
    int e  = i & 3;
    int q  = (i >> 2) & 3;
    int j2 = (i >> 4) & 15;
    int cc = (i >> 8) & 3;
    int k  = (i >> 10) % 9;
    int g  = i / 9216;
    int c  = q*4 + cc;
    int co = j2*4 + e;
    g_wTu[i] = rw[(size_t)(co*Cn + g*CGn + c)*Kn + k];
}

// ---------------------------------------------------------------------------
// Offset conv (known good).
// ---------------------------------------------------------------------------
__global__ void k_offset(const float* __restrict__ wr, const float* __restrict__ src,
                         const float* __restrict__ ow, const float* __restrict__ ob,
                         float* __restrict__ offout) {
    __shared__ float sT[8*18*35];
    __shared__ float sWp[8*9*20];
    int tid = threadIdx.x;
    int g = blockIdx.y, b = blockIdx.z;
    int th = (blockIdx.x / 6) * 16, tw = (blockIdx.x % 6) * 32;
    int lyy = tid >> 4, lxx = tid & 15;

    float4 acc0[5], acc1[5];
    #pragma unroll
    for (int j = 0; j < 5; j++) { acc0[j] = make_float4(0,0,0,0); acc1[j] = make_float4(0,0,0,0); }

    for (int chunk = 0; chunk < 4; chunk++) {
        const float* base = (chunk < 2 ? wr : src) + (size_t)(b*Cn + g*CGn + (chunk&1)*8)*HWn;
        __syncthreads();
        for (int i = tid; i < 1440; i += 256) {
            int c = i / 180; int r = i % 180; int widx = r / 20; int o = r % 20;
            float v = 0.f;
            if (o < 18) v = ow[(size_t)(o*32 + chunk*8 + c)*9 + widx];
            sWp[i] = v;
        }
        for (int i = tid; i < 8*18*35; i += 256) {
            int c = i / 630; int r2 = i % 630; int rr = r2 / 35; int cc = r2 % 35;
            int y = th + rr - 1, x = tw + cc - 1;
            float v = 0.f;
            if (cc < 34 && (unsigned)y < (unsigned)Hn && (unsigned)x < (unsigned)Wn)
                v = base[c*HWn + y*Wn + x];
            sT[i] = v;
        }
        __syncthreads();
        for (int c = 0; c < 8; c++) {
            #pragma unroll
            for (int kh = 0; kh < 3; kh++) {
                const float* rowp = sT + c*630 + (lyy+kh)*35 + 2*lxx;
                float xv[4];
                xv[0] = rowp[0]; xv[1] = rowp[1]; xv[2] = rowp[2]; xv[3] = rowp[3];
                #pragma unroll
                for (int kw = 0; kw < 3; kw++) {
                    const float4* wp = (const float4*)(sWp + (c*9 + kh*3 + kw)*20);
                    float a0 = xv[kw], a1 = xv[kw+1];
                    #pragma unroll
                    for (int j = 0; j < 5; j++) {
                        float4 wv = wp[j];
                        acc0[j].x = fmaf(a0, wv.x, acc0[j].x); acc1[j].x = fmaf(a1, wv.x, acc1[j].x);
                        acc0[j].y = fmaf(a0, wv.y, acc0[j].y); acc1[j].y = fmaf(a1, wv.y, acc1[j].y);
                        acc0[j].z = fmaf(a0, wv.z, acc0[j].z); acc1[j].z = fmaf(a1, wv.z, acc1[j].z);
                        acc0[j].w = fmaf(a0, wv.w, acc0[j].w); acc1[j].w = fmaf(a1, wv.w, acc1[j].w);
                    }
                }
            }
        }
    }
    int h = th + lyy, w = tw + 2*lxx;
    const float* a0 = (const float*)acc0;
    const float* a1 = (const float*)acc1;
    #pragma unroll
    for (int o = 0; o < 18; o++) {
        float bo = ob[o];
        float2 r;
        r.x = 50.f * tanhf(0.5f * (a0[o] + bo));
        r.y = 50.f * tanhf(0.5f * (a1[o] + bo));
        *(float2*)(offout + (size_t)(b*72 + g*18 + o)*HWn + h*Wn + w) = r;
    }
}

// ---------------------------------------------------------------------------
// Modulator conv (known good).
// ---------------------------------------------------------------------------
__global__ void k_mod(const float* __restrict__ wr, const float* __restrict__ mw,
                      const float* __restrict__ mb) {
    __shared__ float sT[8*18*35];
    __shared__ float sWp[8*9*20];
    int tid = threadIdx.x;
    int obase = blockIdx.y * 18;
    int b = blockIdx.z;
    int th = (blockIdx.x / 6) * 16, tw = (blockIdx.x % 6) * 32;
    int lyy = tid >> 4, lxx = tid & 15;

    float4 acc0[5], acc1[5];
    #pragma unroll
    for (int j = 0; j < 5; j++) { acc0[j] = make_float4(0,0,0,0); acc1[j] = make_float4(0,0,0,0); }

    for (int chunk = 0; chunk < 8; chunk++) {
        const float* base = wr + (size_t)(b*Cn + chunk*8)*HWn;
        __syncthreads();
        for (int i = tid; i < 1440; i += 256) {
            int c = i / 180; int r = i % 180; int widx = r / 20; int o = r % 20;
            float v = 0.f;
            if (o < 18) v = mw[(size_t)((obase + o)*Cn + chunk*8 + c)*9 + widx];
            sWp[i] = v;
        }
        for (int i = tid; i < 8*18*35; i += 256) {
            int c = i / 630; int r2 = i % 630; int rr = r2 / 35; int cc = r2 % 35;
            int y = th + rr - 1, x = tw + cc - 1;
            float v = 0.f;
            if (cc < 34 && (unsigned)y < (unsigned)Hn && (unsigned)x < (unsigned)Wn)
                v = base[c*HWn + y*Wn + x];
            sT[i] = v;
        }
        __syncthreads();
        for (int c = 0; c < 8; c++) {
            #pragma unroll
            for (int kh = 0; kh < 3; kh++) {
                const float* rowp = sT + c*630 + (lyy+kh)*35 + 2*lxx;
                float xv[4];
                xv[0] = rowp[0]; xv[1] = rowp[1]; xv[2] = rowp[2]; xv[3] = rowp[3];
                #pragma unroll
                for (int kw = 0; kw < 3; kw++) {
                    const float4* wp = (const float4*)(sWp + (c*9 + kh*3 + kw)*20);
                    float a0 = xv[kw], a1 = xv[kw+1];
                    #pragma unroll
                    for (int j = 0; j < 5; j++) {
                        float4 wv = wp[j];
                        acc0[j].x = fmaf(a0, wv.x, acc0[j].x); acc1[j].x = fmaf(a1, wv.x, acc1[j].x);
                        acc0[j].y = fmaf(a0, wv.y, acc0[j].y); acc1[j].y = fmaf(a1, wv.y, acc1[j].y);
                        acc0[j].z = fmaf(a0, wv.z, acc0[j].z); acc1[j].z = fmaf(a1, wv.z, acc1[j].z);
                        acc0[j].w = fmaf(a0, wv.w, acc0[j].w); acc1[j].w = fmaf(a1, wv.w, acc1[j].w);
                    }
                }
            }
        }
    }
    int h = th + lyy, w = tw + 2*lxx;
    const float* a0 = (const float*)acc0;
    const float* a1 = (const float*)acc1;
    #pragma unroll
    for (int o = 0; o < 18; o++) {
        float bo = mb[obase + o];
        float2 r;
        r.x = 1.f + tanhf(0.5f * (a0[o] + bo));
        r.y = 1.f + tanhf(0.5f * (a1[o] + bo));
        *(float2*)(g_mod + (size_t)(b*36 + obase + o)*HWn + h*Wn + w) = r;
    }
}

// ---------------------------------------------------------------------------
// Deformable conv, exchange-free, q-interleaved weights.
// Thread = (pixel, channel-quad q). Lane q gathers channels q*4..q*4+3
// (4 lanes/pixel -> 64B contiguous per bilinear corner) and contracts them
// into ALL 64 output channels (32 f32x2 partial accs). Weight smem layout
// [k][cc][j2][q][4] puts the 4 q-lanes 16B apart (banks 0/4/8/12,
// 8-px broadcast) -> conflict-free LDS.128. One butterfly at the end.
// ---------------------------------------------------------------------------
__global__ void __launch_bounds__(256, 2) k_deform(
        const float* __restrict__ offmap, float* __restrict__ out) {
    __shared__ float sW[Kn*4*16*4*4];   // 9216 floats = 36 KB
    int tid  = threadIdx.x;
    int lane = tid & 31;
    int pxw  = lane >> 2;            // pixel within warp (0..7)
    int q    = lane & 3;             // channel-quad (0..3)
    int px   = (tid >> 5)*8 + pxw;   // pixel within block (0..63)
    int p0   = blockIdx.x * 64;
    int b    = p0 / HWn;
    int hw   = p0 - b*HWn + px;
    int h    = hw / Wn, w = hw - h*Wn;

    ull acc[32];
    #pragma unroll
    for (int j = 0; j < 32; j++) acc[j] = 0ull;

    const float* xb = g_xnhwc + (size_t)b*HWn*Cn;

    for (int g = 0; g < Gn; g++) {
        __syncthreads();
        {   // coalesced linear copy (pre-baked layout)
            const float* wg = g_wTu + g*9216;
            for (int i = tid; i < 9216; i += 256) sW[i] = wg[i];
        }
        __syncthreads();

        const float* offb = offmap + (size_t)(b*72 + g*18)*HWn + hw;
        const float* modb = g_mod  + (size_t)(b*36 + g*9 )*HWn + hw;
        const float* xg   = xb + g*CGn + q*4;

        #pragma unroll 1
        for (int k = 0; k < 9; k++) {
            // ---- gather: this lane's 4 channels of its pixel ----
            float oy = offb[(2*k  )*HWn];
            float ox = offb[(2*k+1)*HWn];
            float m  = modb[k*HWn];
            float yf = oy + (float)(k/3 + h - 1);
            float xf = ox + (float)(k%3 + w - 1);
            float y0f = floorf(yf), x0f = floorf(xf);
            int   y0  = (int)y0f,   x0  = (int)x0f;
            float ly = yf - y0f, lx = xf - x0f;
            float cw0 = (1.f-ly)*(1.f-lx)*m;
            float cw1 = (1.f-ly)*lx*m;
            float cw2 = ly*(1.f-lx)*m;
            float cw3 = ly*lx*m;
            float4 v = make_float4(0.f,0.f,0.f,0.f);
            #pragma unroll
            for (int corner = 0; corner < 4; corner++) {
                int yi = y0 + (corner >> 1);
                int xi = x0 + (corner & 1);
                float wc = (corner==0)?cw0:(corner==1)?cw1:(corner==2)?cw2:cw3;
                if ((unsigned)yi < (unsigned)Hn && (unsigned)xi < (unsigned)Wn) {
                    float4 xv = *(const float4*)(xg + (size_t)(yi*Wn + xi)*Cn);
                    v.x = fmaf(wc, xv.x, v.x);
                    v.y = fmaf(wc, xv.y, v.y);
                    v.z = fmaf(wc, xv.z, v.z);
                    v.w = fmaf(wc, xv.w, v.w);
                }
            }
            // ---- contract my 4 channels into all 64 co ----
            float cv[4] = {v.x, v.y, v.z, v.w};
            #pragma unroll
            for (int cc = 0; cc < 4; cc++) {
                ull vp = pk2(cv[cc]);
                // row for (k, cc): 16 j2-slots, this lane offset q*4 floats
                const float* rp = sW + ((k*4 + cc)*16)*16 + q*4;
                #pragma unroll
                for (int j2 = 0; j2 < 16; j2++) {
                    ulonglong2 wv = *(const ulonglong2*)(rp + j2*16);
                    fma2(acc[2*j2],   vp, wv.x);
                    fma2(acc[2*j2+1], vp, wv.y);
                }
            }
        }
    }

    // ---- one-time butterfly reduction over the 4 q-lanes of each pixel ----
    float2 af[32];
    #pragma unroll
    for (int t = 0; t < 32; t++) af[t] = upk(acc[t]);
    #pragma unroll
    for (int t = 0; t < 32; t++) {
        af[t].x += __shfl_xor_sync(0xffffffffu, af[t].x, 1);
        af[t].y += __shfl_xor_sync(0xffffffffu, af[t].y, 1);
        af[t].x += __shfl_xor_sync(0xffffffffu, af[t].x, 2);
        af[t].y += __shfl_xor_sync(0xffffffffu, af[t].y, 2);
    }

    // lane q writes co pairs t = q*8 .. q*8+7  (co = 2t, 2t+1)
    float* ob = out + (size_t)b*Cn*HWn + hw;
    #pragma unroll
    for (int r = 0; r < 8; r++) {
        int t = q*8 + r;
        ob[(size_t)(2*t  )*HWn] = af[t].x;
        ob[(size_t)(2*t+1)*HWn] = af[t].y;
    }
}

// ---------------------------------------------------------------------------
extern "C" void kernel_launch(void* const* d_in, const int* in_sizes, int n_in,
                              void* d_out, int out_size) {
    const float* wr  = (const float*)d_in[0];
    const float* src = (const float*)d_in[1];
    const float* ow  = (const float*)d_in[2];
    const float* obv = (const float*)d_in[3];
    const float* mw  = (const float*)d_in[4];
    const float* mbv = (const float*)d_in[5];
    const float* rw  = (const float*)d_in[6];

    float* out    = (float*)d_out;
    float* offout = out + (size_t)Bn*Cn*HWn;

    k_transpose<<<dim3(HWn/32, 2, Bn), dim3(32, 8)>>>(wr);
    k_wprep   <<<(Gn*Kn*4*16*4*4 + 255)/256, 256>>>(rw);
    k_offset  <<<dim3(72, Gn, Bn), 256>>>(wr, src, ow, obv, offout);
    k_mod     <<<dim3(72, 2, Bn), 256>>>(wr, mw, mbv);
    k_deform  <<<Bn*HWn/64, 256>>>(offout, out);
}